// round 12
// baseline (speedup 1.0000x reference)
#include <cuda_runtime.h>
#include <cstdint>

// Problem dims (fixed by the dataset)
#define N_  64
#define C_  256
#define T_  64
#define V_  50
#define H_  16
#define P_  10
#define TV  3200               // floats per (n,c) slab

#define SLABS 8                // batches handled per block
#define GRPS  (N_ / SLABS)     // 8 independent groups of 256 blocks
#define NBLK  (GRPS * C_)      // 2048 blocks

// output column j -> input column v (concat order of PARTS)
__constant__ int c_cmap[V_] = {
    0,1,2,3,20,
    8,9,10,11,23,24,
    16,17,18,19,
    4,5,6,7,21,22,
    12,13,14,15,
    25,26,27,28,45,
    33,34,35,36,48,49,
    41,42,43,44,
    29,30,31,32,46,47,
    37,38,39,40
};
// output column j -> partition
__constant__ int c_pmap[V_] = {
    0,0,0,0,0,
    1,1,1,1,1,1,
    2,2,2,2,
    3,3,3,3,3,3,
    4,4,4,4,
    5,5,5,5,5,
    6,6,6,6,6,6,
    7,7,7,7,
    8,8,8,8,8,8,
    9,9,9,9
};
// partition -> member input columns (padded to 6) and sizes
__constant__ int c_pvs[P_ * 6] = {
    0,1,2,3,20,0,
    8,9,10,11,23,24,
    16,17,18,19,0,0,
    4,5,6,7,21,22,
    12,13,14,15,0,0,
    25,26,27,28,45,0,
    33,34,35,36,48,49,
    41,42,43,44,0,0,
    29,30,31,32,46,47,
    37,38,39,40,0,0
};
__constant__ int c_psize[P_] = {5,6,4,6,4,5,6,4,6,4};

// Scratch (alloc-free rule: __device__ globals).
__device__ float    g_avg [N_ * P_ * C_];    // [n][p][c]
__device__ float    g_max [N_ * P_ * C_];
__device__ float    g_h   [N_ * P_ * H_];    // [n][p][i]
__device__ unsigned g_cnt [N_];              // monotonic tickets (replay-safe)
__device__ unsigned g_hcnt[N_];              // monotonic h-ready counters

// ---------------------------------------------------------------------------
// Pipelined fused kernel. Block (grp, c) handles slabs (n = grp*8+s, c),
// s = 0..7, with a depth-2 smem pipeline:
//   publish(0); publish(1); for s: { wait h(s); scale(s); publish(s+2); }
// A block is never idle-waiting unless peer skew exceeds ~2 slab-times.
// x touches the LTS/DRAM path exactly once.
// ---------------------------------------------------------------------------
__global__ __launch_bounds__(256)
void fused_kernel(const float4* __restrict__ x4,
                  const float* __restrict__ W1, const float* __restrict__ b1,
                  const float* __restrict__ W2, const float* __restrict__ b2,
                  float* __restrict__ out)
{
    __shared__ float    buf[2][TV];         // 25.6 KB double buffer
    __shared__ float    ps[200], pm[200];
    __shared__ float    cs[V_ + 2], cmx[V_ + 2];
    __shared__ float    hsm[P_ * H_];
    __shared__ float    gch[P_ + 2];
    __shared__ float2   tab[V_ + 2];
    __shared__ unsigned stk[SLABS];

    const int tid = threadIdx.x;
    const int grp = blockIdx.x >> 8;
    const int c   = blockIdx.x & 255;
    const int w   = tid >> 5;
    const int l   = tid & 31;

    // ---- stage slab s into buf[bi], reduce, publish partials, ticket,
    //      and (if last ticket of the batch) finalize h ----------------------
    auto reduce_publish = [&](int s, int bi) {
        const int n  = grp * SLABS + s;
        const int nc = n * C_ + c;

        const float4* xb = x4 + (size_t)nc * (TV / 4);
        float4* b4 = (float4*)buf[bi];
#pragma unroll
        for (int k = 0; k < 3; ++k)
            b4[tid + 256 * k] = xb[tid + 256 * k];
        if (tid < 32)
            b4[tid + 768] = xb[tid + 768];
        __syncthreads();

        if (tid < 200) {                    // 50 cols x 4 row-groups of 16
            const int col = tid % V_;
            const int r0  = (tid / V_) * 16;
            float s1 = 0.f, m1 = -3.402823466e+38f;
#pragma unroll
            for (int rr = 0; rr < 16; ++rr) {
                const float v = buf[bi][(r0 + rr) * V_ + col];
                s1 += v;
                m1 = fmaxf(m1, v);
            }
            ps[tid] = s1;
            pm[tid] = m1;
        }
        __syncthreads();
        if (tid < V_) {
            cs[tid]  = ps[tid] + ps[tid + 50] + ps[tid + 100] + ps[tid + 150];
            cmx[tid] = fmaxf(fmaxf(pm[tid], pm[tid + 50]),
                             fmaxf(pm[tid + 100], pm[tid + 150]));
        }
        __syncthreads();
        if (tid < P_) {
            const int sz = c_psize[tid];
            float s3 = 0.f, m3 = -3.402823466e+38f;
            for (int j = 0; j < sz; ++j) {
                const int vv = c_pvs[tid * 6 + j];
                s3 += cs[vv];
                m3 = fmaxf(m3, cmx[vv]);
            }
            const size_t o = ((size_t)n * P_ + tid) * C_ + c;
            g_avg[o] = s3 / (float)(T_ * sz);
            g_max[o] = m3;
            __threadfence();                // release partials
        }
        __syncthreads();
        if (tid == 0)
            stk[s] = atomicAdd(&g_cnt[n], 1u);
        __syncthreads();

        if ((stk[s] & 255u) == 255u) {
            // this block saw the last publish of batch n this run: finalize h
            __threadfence();                // acquire peers' partials
#pragma unroll
            for (int p = 0; p < P_; ++p) {
#pragma unroll
                for (int ii = 0; ii < 2; ++ii) {
                    const int i = w + 8 * ii;
                    const float* w1 = W1 + ((size_t)p * H_ + i) * C_;
                    const float* av = g_avg + ((size_t)n * P_ + p) * C_;
                    const float* mx = g_max + ((size_t)n * P_ + p) * C_;
                    float da = 0.f, dm = 0.f;
#pragma unroll
                    for (int k = 0; k < 8; ++k) {
                        const int cc = l + 32 * k;
                        const float wv = w1[cc];
                        da += wv * av[cc];
                        dm += wv * mx[cc];
                    }
#pragma unroll
                    for (int off = 16; off > 0; off >>= 1) {
                        da += __shfl_down_sync(0xffffffffu, da, off);
                        dm += __shfl_down_sync(0xffffffffu, dm, off);
                    }
                    if (l == 0) {
                        const float bb = b1[p * H_ + i];
                        g_h[((size_t)n * P_ + p) * H_ + i] =
                            fmaxf(da + bb, 0.f) + fmaxf(dm + bb, 0.f);
                        __threadfence();    // release h
                    }
                }
            }
            __syncthreads();
            if (tid == 0)
                atomicAdd(&g_hcnt[n], 1u);
        }
    };

    // ---- wait for h(batch s), compute gates for channel c, scale buf[bi] ---
    auto consume = [&](int s, int bi) {
        const int n   = grp * SLABS + s;
        const int nc  = n * C_ + c;
        const unsigned run = stk[s] >> 8;   // replay index (monotonic)

        if (tid == 0) {
            while (*(volatile unsigned*)&g_hcnt[n] < run + 1u)
                __nanosleep(64);
        }
        __syncthreads();
        __threadfence();                    // acquire h

        if (tid < P_ * H_)
            hsm[tid] = g_h[(size_t)n * P_ * H_ + tid];
        __syncthreads();

        if (tid < P_) {
            const int p = tid;
            const float* w2 = W2 + ((size_t)p * C_ + c) * H_;
            float acc = 2.f * b2[p * C_ + c];
#pragma unroll
            for (int i = 0; i < H_; ++i)
                acc += w2[i] * hsm[p * H_ + i];
            gch[p] = 1.f / (1.f + __expf(-acc));
        }
        __syncthreads();
        if (tid < V_) {
            float2 t;
            t.x = gch[c_pmap[tid]];
            t.y = __int_as_float(c_cmap[tid] - tid);
            tab[tid] = t;
        }
        __syncthreads();

        float* ob = out + (size_t)nc * TV;
        int col = tid % V_;
#pragma unroll
        for (int m = 0; m < 13; ++m) {
            if (m < 12 || tid < 128) {
                const int jj = tid + 256 * m;
                const float2 t = tab[col];
                __stcs(&ob[jj], buf[bi][jj + __float_as_int(t.y)] * t.x);
            }
            col += 6;                       // 256 mod 50
            if (col >= V_) col -= V_;
        }
        __syncthreads();                    // buffer free for reuse
    };

    // ---- depth-2 pipeline over this block's 8 slabs -----------------------
    reduce_publish(0, 0);
    reduce_publish(1, 1);
#pragma unroll 1
    for (int s = 0; s < SLABS; ++s) {
        consume(s, s & 1);
        if (s + 2 < SLABS)
            reduce_publish(s + 2, s & 1);
    }
}

// ---------------------------------------------------------------------------
extern "C" void kernel_launch(void* const* d_in, const int* in_sizes, int n_in,
                              void* d_out, int out_size)
{
    const float* x  = (const float*)d_in[0];
    const float* W1 = (const float*)d_in[1];
    const float* b1 = (const float*)d_in[2];
    const float* W2 = (const float*)d_in[3];
    const float* b2 = (const float*)d_in[4];

    fused_kernel<<<NBLK, 256>>>((const float4*)x, W1, b1, W2, b2,
                                (float*)d_out);
}

// round 13
// speedup vs baseline: 7.9789x; 7.9789x over previous
#include <cuda_runtime.h>
#include <cstdint>

// Problem dims (fixed by the dataset)
#define N_  64
#define C_  256
#define T_  64
#define V_  50
#define H_  16
#define P_  10
#define TV  (T_ * V_)          // 3200 floats per (n,c) slab

#define HALF_NC  (N_ * C_ / 2)     // 8192 slabs per half
#define HALF_NP  (N_ * P_ / 2)     // 320 gate groups per half

// output column j -> input column v (concat order of PARTS)
__constant__ int c_cmap[V_] = {
    0,1,2,3,20,
    8,9,10,11,23,24,
    16,17,18,19,
    4,5,6,7,21,22,
    12,13,14,15,
    25,26,27,28,45,
    33,34,35,36,48,49,
    41,42,43,44,
    29,30,31,32,46,47,
    37,38,39,40
};
// output column j -> partition
__constant__ int c_pmap[V_] = {
    0,0,0,0,0,
    1,1,1,1,1,1,
    2,2,2,2,
    3,3,3,3,3,3,
    4,4,4,4,
    5,5,5,5,5,
    6,6,6,6,6,6,
    7,7,7,7,
    8,8,8,8,8,8,
    9,9,9,9
};
// partition -> member input columns (padded to 6) and sizes
__constant__ int c_pvs[P_ * 6] = {
    0,1,2,3,20,0,
    8,9,10,11,23,24,
    16,17,18,19,0,0,
    4,5,6,7,21,22,
    12,13,14,15,0,0,
    25,26,27,28,45,0,
    33,34,35,36,48,49,
    41,42,43,44,0,0,
    29,30,31,32,46,47,
    37,38,39,40,0,0
};
__constant__ int c_psize[P_] = {5,6,4,6,4,5,6,4,6,4};

// Scratch (alloc-free rule: __device__ globals). Layout: [n][p][c]
__device__ float g_avg [N_ * P_ * C_];
__device__ float g_max [N_ * P_ * C_];
__device__ float g_gate[N_ * P_ * C_];

// ---------------------------------------------------------------------------
// Kernel 1: per-(n,c) sum+max over (t, v in part) for all 10 parts.
// One WARP per (n,c) slab; lanes 0..24 own a column-pair as float2.
// (Best measured reduce variant: 36.0us standalone, 74.9% DRAM.)
// ---------------------------------------------------------------------------
__global__ __launch_bounds__(256)
void reduce_kernel(const float2* __restrict__ x2, int nc0)
{
    __shared__ float cs [8][V_ + 2];
    __shared__ float cmx[8][V_ + 2];

    const int warp = threadIdx.x >> 5;
    const int lane = threadIdx.x & 31;
    const int nc   = nc0 + blockIdx.x * 8 + warp;    // n*C_ + c

    if (lane < 25) {
        const float2* p = x2 + (size_t)nc * (TV / 2) + lane;
        float sx = 0.f, sy = 0.f;
        float mx = -3.402823466e+38f, my = -3.402823466e+38f;
#pragma unroll 8
        for (int r = 0; r < T_; ++r) {
            float2 v = p[r * 25];
            sx += v.x;             sy += v.y;
            mx = fmaxf(mx, v.x);   my = fmaxf(my, v.y);
        }
        cs [warp][2 * lane]     = sx;
        cs [warp][2 * lane + 1] = sy;
        cmx[warp][2 * lane]     = mx;
        cmx[warp][2 * lane + 1] = my;
    }
    __syncwarp();

    if (lane < P_) {
        const int sz = c_psize[lane];
        float s3 = 0.f, m3 = -3.402823466e+38f;
        for (int j = 0; j < sz; ++j) {
            const int vv = c_pvs[lane * 6 + j];
            s3 += cs[warp][vv];
            m3 = fmaxf(m3, cmx[warp][vv]);
        }
        const int n = nc >> 8;      // C_ = 256
        const int c = nc & 255;
        const size_t o = ((size_t)n * P_ + lane) * C_ + c;
        g_avg[o] = s3 / (float)(T_ * sz);
        g_max[o] = m3;
    }
}

// ---------------------------------------------------------------------------
// Kernel 2: gate[n,p,c] = sigmoid( W2 @ (relu(W1@avg+b1)+relu(W1@mx+b1)) + 2*b2 )
// One block per (n,p), 256 threads.
// ---------------------------------------------------------------------------
__global__ __launch_bounds__(C_)
void gate_kernel(const float* __restrict__ W1, const float* __restrict__ b1,
                 const float* __restrict__ W2, const float* __restrict__ b2,
                 int np0)
{
    const int np = np0 + blockIdx.x;
    const int n  = np / P_;
    const int p  = np % P_;
    const int tid = threadIdx.x;

    __shared__ float sa[C_];
    __shared__ float sx[C_];
    __shared__ float hs[H_];

    const size_t base = ((size_t)n * P_ + p) * C_;
    sa[tid] = g_avg[base + tid];
    sx[tid] = g_max[base + tid];
    __syncthreads();

    const int w = tid >> 5;     // warp 0..7
    const int l = tid & 31;

#pragma unroll
    for (int ii = 0; ii < 2; ++ii) {
        const int i = w + 8 * ii;
        const float* w1 = W1 + ((size_t)p * H_ + i) * C_;
        float da = 0.f, dm = 0.f;
#pragma unroll
        for (int k = 0; k < 8; ++k) {
            const int c = l + 32 * k;
            const float wv = w1[c];
            da += wv * sa[c];
            dm += wv * sx[c];
        }
#pragma unroll
        for (int off = 16; off > 0; off >>= 1) {
            da += __shfl_down_sync(0xffffffffu, da, off);
            dm += __shfl_down_sync(0xffffffffu, dm, off);
        }
        if (l == 0) {
            const float bb = b1[p * H_ + i];
            hs[i] = fmaxf(da + bb, 0.f) + fmaxf(dm + bb, 0.f);
        }
    }
    __syncthreads();

    const float* w2 = W2 + ((size_t)p * C_ + tid) * H_;
    float acc = 2.f * b2[p * C_ + tid];
#pragma unroll
    for (int k = 0; k < H_; ++k)
        acc += w2[k] * hs[k];

    g_gate[base + tid] = 1.f / (1.f + __expf(-acc));
}

// ---------------------------------------------------------------------------
// Kernel 3: out[n,c,t,j] = x[n,c,t,cmap[j]] * gate[n, pmap[j], c]
// smem-staged float4 reads, streaming stores. (Best measured scale variant.)
// ---------------------------------------------------------------------------
__global__ __launch_bounds__(256)
void scale_kernel(const float4* __restrict__ x4, float* __restrict__ out,
                  int nc0)
{
    __shared__ float4 sh4[TV / 4];          // 12.8 KB
    __shared__ float2 tab[V_ + 2];          // {gate, int_as_float(cmap[j]-j)}
    float* sh = (float*)sh4;

    const int nc  = nc0 + blockIdx.x;
    const int tid = threadIdx.x;
    const int n = nc >> 8;
    const int c = nc & 255;

    const float4* xb = x4  + (size_t)nc * (TV / 4);
    float*        ob = out + (size_t)nc * TV;

    // Phase A: coalesced float4 loads into shared; threads <50 stage table
#pragma unroll
    for (int k = 0; k < 3; ++k)
        sh4[tid + 256 * k] = xb[tid + 256 * k];
    if (tid < 32)
        sh4[tid + 768] = xb[tid + 768];
    if (tid < V_) {
        const int j = tid;
        float2 t;
        t.x = g_gate[((size_t)n * P_ + c_pmap[j]) * C_ + c];
        t.y = __int_as_float(c_cmap[j] - j);
        tab[j] = t;
    }
    __syncthreads();

    // Phase B: lane-consecutive elements jj = tid + 256*m (3200 = 12*256+128)
    int col = tid % V_;                 // output column of element tid
#pragma unroll
    for (int m = 0; m < 13; ++m) {
        if (m < 12 || tid < 128) {
            const int jj = tid + 256 * m;
            const float2 t = tab[col];
            __stcs(&ob[jj], sh[jj + __float_as_int(t.y)] * t.x);
        }
        // advance column by 256 mod 50 = 6
        col += 6;
        if (col >= V_) col -= V_;
    }
}

// ---------------------------------------------------------------------------
// Two half-pipelines on separate streams, fork-join via events (capturable).
// Overlap hides the gate kernels and inter-kernel ramp bubbles.
// ---------------------------------------------------------------------------
extern "C" void kernel_launch(void* const* d_in, const int* in_sizes, int n_in,
                              void* d_out, int out_size)
{
    const float* x  = (const float*)d_in[0];
    const float* W1 = (const float*)d_in[1];
    const float* b1 = (const float*)d_in[2];
    const float* W2 = (const float*)d_in[3];
    const float* b2 = (const float*)d_in[4];
    float* out = (float*)d_out;

    static cudaStream_t s1, s2;
    static cudaEvent_t  evRoot, ev1, ev2;
    static int inited = 0;
    if (!inited) {
        cudaStreamCreateWithFlags(&s1, cudaStreamNonBlocking);
        cudaStreamCreateWithFlags(&s2, cudaStreamNonBlocking);
        cudaEventCreateWithFlags(&evRoot, cudaEventDisableTiming);
        cudaEventCreateWithFlags(&ev1,    cudaEventDisableTiming);
        cudaEventCreateWithFlags(&ev2,    cudaEventDisableTiming);
        inited = 1;
    }

    // fork from the launch (capture) stream
    cudaEventRecord(evRoot, 0);
    cudaStreamWaitEvent(s1, evRoot, 0);
    cudaStreamWaitEvent(s2, evRoot, 0);

    // half A on s1
    reduce_kernel<<<HALF_NC / 8, 256, 0, s1>>>((const float2*)x, 0);
    gate_kernel  <<<HALF_NP,     C_,  0, s1>>>(W1, b1, W2, b2, 0);
    scale_kernel <<<HALF_NC,     256, 0, s1>>>((const float4*)x, out, 0);

    // half B on s2
    reduce_kernel<<<HALF_NC / 8, 256, 0, s2>>>((const float2*)x, HALF_NC);
    gate_kernel  <<<HALF_NP,     C_,  0, s2>>>(W1, b1, W2, b2, HALF_NP);
    scale_kernel <<<HALF_NC,     256, 0, s2>>>((const float4*)x, out, HALF_NC);

    // join back to the launch stream
    cudaEventRecord(ev1, s1);
    cudaEventRecord(ev2, s2);
    cudaStreamWaitEvent(0, ev1, 0);
    cudaStreamWaitEvent(0, ev2, 0);
}

// round 14
// speedup vs baseline: 8.2244x; 1.0308x over previous
#include <cuda_runtime.h>
#include <cstdint>

// Problem dims (fixed by the dataset)
#define N_  64
#define C_  256
#define T_  64
#define V_  50
#define H_  16
#define P_  10
#define TV  (T_ * V_)          // 3200 floats per (n,c) slab

// output column j -> input column v (concat order of PARTS)
__constant__ int c_cmap[V_] = {
    0,1,2,3,20,
    8,9,10,11,23,24,
    16,17,18,19,
    4,5,6,7,21,22,
    12,13,14,15,
    25,26,27,28,45,
    33,34,35,36,48,49,
    41,42,43,44,
    29,30,31,32,46,47,
    37,38,39,40
};
// output column j -> partition
__constant__ int c_pmap[V_] = {
    0,0,0,0,0,
    1,1,1,1,1,1,
    2,2,2,2,
    3,3,3,3,3,3,
    4,4,4,4,
    5,5,5,5,5,
    6,6,6,6,6,6,
    7,7,7,7,
    8,8,8,8,8,8,
    9,9,9,9
};
// partition -> member input columns (padded to 6) and sizes
__constant__ int c_pvs[P_ * 6] = {
    0,1,2,3,20,0,
    8,9,10,11,23,24,
    16,17,18,19,0,0,
    4,5,6,7,21,22,
    12,13,14,15,0,0,
    25,26,27,28,45,0,
    33,34,35,36,48,49,
    41,42,43,44,0,0,
    29,30,31,32,46,47,
    37,38,39,40,0,0
};
__constant__ int c_psize[P_] = {5,6,4,6,4,5,6,4,6,4};

// Scratch (alloc-free rule: __device__ globals). Layout: [n][p][c]
__device__ float g_avg [N_ * P_ * C_];
__device__ float g_max [N_ * P_ * C_];
__device__ float g_gate[N_ * P_ * C_];

// ---------------------------------------------------------------------------
// Kernel 1: per-(n,c) sum+max over (t, v in part) for all 10 parts.
// One WARP per (n,c) slab; lanes 0..24 own a column-pair as float2.
// Deeper unroll (16) => 16 outstanding LDG.64 per lane for latency coverage.
// ---------------------------------------------------------------------------
__global__ __launch_bounds__(256)
void reduce_kernel(const float2* __restrict__ x2)
{
    __shared__ float cs [8][V_ + 2];
    __shared__ float cmx[8][V_ + 2];

    const int warp = threadIdx.x >> 5;
    const int lane = threadIdx.x & 31;
    const int nc   = blockIdx.x * 8 + warp;          // n*C_ + c

    if (lane < 25) {
        const float2* p = x2 + (size_t)nc * (TV / 2) + lane;
        float sx = 0.f, sy = 0.f;
        float mx = -3.402823466e+38f, my = -3.402823466e+38f;
#pragma unroll 16
        for (int r = 0; r < T_; ++r) {
            float2 v = p[r * 25];
            sx += v.x;             sy += v.y;
            mx = fmaxf(mx, v.x);   my = fmaxf(my, v.y);
        }
        cs [warp][2 * lane]     = sx;
        cs [warp][2 * lane + 1] = sy;
        cmx[warp][2 * lane]     = mx;
        cmx[warp][2 * lane + 1] = my;
    }
    __syncwarp();

    if (lane < P_) {
        const int sz = c_psize[lane];
        float s3 = 0.f, m3 = -3.402823466e+38f;
        for (int j = 0; j < sz; ++j) {
            const int vv = c_pvs[lane * 6 + j];
            s3 += cs[warp][vv];
            m3 = fmaxf(m3, cmx[warp][vv]);
        }
        const int n = nc >> 8;      // C_ = 256
        const int c = nc & 255;
        const size_t o = ((size_t)n * P_ + lane) * C_ + c;
        g_avg[o] = s3 / (float)(T_ * sz);
        g_max[o] = m3;
    }
}

// ---------------------------------------------------------------------------
// Kernel 2: gate[n,p,c] = sigmoid( W2 @ (relu(W1@avg+b1)+relu(W1@mx+b1)) + 2*b2 )
// One block per (n,p), 256 threads.
// ---------------------------------------------------------------------------
__global__ __launch_bounds__(C_)
void gate_kernel(const float* __restrict__ W1, const float* __restrict__ b1,
                 const float* __restrict__ W2, const float* __restrict__ b2)
{
    const int np = blockIdx.x;
    const int n  = np / P_;
    const int p  = np % P_;
    const int tid = threadIdx.x;

    __shared__ float sa[C_];
    __shared__ float sx[C_];
    __shared__ float hs[H_];

    const size_t base = ((size_t)n * P_ + p) * C_;
    sa[tid] = g_avg[base + tid];
    sx[tid] = g_max[base + tid];
    __syncthreads();

    const int w = tid >> 5;     // warp 0..7
    const int l = tid & 31;

#pragma unroll
    for (int ii = 0; ii < 2; ++ii) {
        const int i = w + 8 * ii;
        const float* w1 = W1 + ((size_t)p * H_ + i) * C_;
        float da = 0.f, dm = 0.f;
#pragma unroll
        for (int k = 0; k < 8; ++k) {
            const int c = l + 32 * k;
            const float wv = w1[c];
            da += wv * sa[c];
            dm += wv * sx[c];
        }
#pragma unroll
        for (int off = 16; off > 0; off >>= 1) {
            da += __shfl_down_sync(0xffffffffu, da, off);
            dm += __shfl_down_sync(0xffffffffu, dm, off);
        }
        if (l == 0) {
            const float bb = b1[p * H_ + i];
            hs[i] = fmaxf(da + bb, 0.f) + fmaxf(dm + bb, 0.f);
        }
    }
    __syncthreads();

    const float* w2 = W2 + ((size_t)p * C_ + tid) * H_;
    float acc = 2.f * b2[p * C_ + tid];
#pragma unroll
    for (int k = 0; k < H_; ++k)
        acc += w2[k] * hs[k];

    g_gate[base + tid] = 1.f / (1.f + __expf(-acc));
}

// ---------------------------------------------------------------------------
// Kernel 3: out[n,c,t,j] = x[n,c,t,cmap[j]] * gate[n, pmap[j], c]
// smem-staged float4 reads (__ldcs: x slab is dead after this read), REVERSE
// block order (consume the x tail reduce left in L2 first), streaming stores.
// ---------------------------------------------------------------------------
__global__ __launch_bounds__(256)
void scale_kernel(const float4* __restrict__ x4, float* __restrict__ out)
{
    __shared__ float4 sh4[TV / 4];          // 12.8 KB
    __shared__ float2 tab[V_ + 2];          // {gate, int_as_float(cmap[j]-j)}
    float* sh = (float*)sh4;

    const int nc  = (N_ * C_ - 1) - blockIdx.x;      // REVERSE order
    const int tid = threadIdx.x;
    const int n = nc >> 8;
    const int c = nc & 255;

    const float4* xb = x4  + (size_t)nc * (TV / 4);
    float*        ob = out + (size_t)nc * TV;

    // Phase A: coalesced float4 loads (evict-first) into shared
#pragma unroll
    for (int k = 0; k < 3; ++k)
        sh4[tid + 256 * k] = __ldcs(&xb[tid + 256 * k]);
    if (tid < 32)
        sh4[tid + 768] = __ldcs(&xb[tid + 768]);
    if (tid < V_) {
        const int j = tid;
        float2 t;
        t.x = g_gate[((size_t)n * P_ + c_pmap[j]) * C_ + c];
        t.y = __int_as_float(c_cmap[j] - j);
        tab[j] = t;
    }
    __syncthreads();

    // Phase B: lane-consecutive elements jj = tid + 256*m (3200 = 12*256+128)
    int col = tid % V_;                 // output column of element tid
#pragma unroll
    for (int m = 0; m < 13; ++m) {
        if (m < 12 || tid < 128) {
            const int jj = tid + 256 * m;
            const float2 t = tab[col];
            __stcs(&ob[jj], sh[jj + __float_as_int(t.y)] * t.x);
        }
        // advance column by 256 mod 50 = 6
        col += 6;
        if (col >= V_) col -= V_;
    }
}

// ---------------------------------------------------------------------------
extern "C" void kernel_launch(void* const* d_in, const int* in_sizes, int n_in,
                              void* d_out, int out_size)
{
    const float* x  = (const float*)d_in[0];
    const float* W1 = (const float*)d_in[1];
    const float* b1 = (const float*)d_in[2];
    const float* W2 = (const float*)d_in[3];
    const float* b2 = (const float*)d_in[4];

    reduce_kernel<<<(N_ * C_) / 8, 256>>>((const float2*)x);
    gate_kernel<<<N_ * P_, C_>>>(W1, b1, W2, b2);
    scale_kernel<<<N_ * C_, 256>>>((const float4*)x, (float*)d_out);
}

// round 15
// speedup vs baseline: 8.2781x; 1.0065x over previous
#include <cuda_runtime.h>
#include <cstdint>

// Problem dims (fixed by the dataset)
#define N_  64
#define C_  256
#define T_  64
#define V_  50
#define H_  16
#define P_  10
#define TV  (T_ * V_)          // 3200 floats per (n,c) slab

// output column j -> input column v (concat order of PARTS)
__constant__ int c_cmap[V_] = {
    0,1,2,3,20,
    8,9,10,11,23,24,
    16,17,18,19,
    4,5,6,7,21,22,
    12,13,14,15,
    25,26,27,28,45,
    33,34,35,36,48,49,
    41,42,43,44,
    29,30,31,32,46,47,
    37,38,39,40
};
// output column j -> partition
__constant__ int c_pmap[V_] = {
    0,0,0,0,0,
    1,1,1,1,1,1,
    2,2,2,2,
    3,3,3,3,3,3,
    4,4,4,4,
    5,5,5,5,5,
    6,6,6,6,6,6,
    7,7,7,7,
    8,8,8,8,8,8,
    9,9,9,9
};
// partition -> member input columns (padded to 6) and sizes
__constant__ int c_pvs[P_ * 6] = {
    0,1,2,3,20,0,
    8,9,10,11,23,24,
    16,17,18,19,0,0,
    4,5,6,7,21,22,
    12,13,14,15,0,0,
    25,26,27,28,45,0,
    33,34,35,36,48,49,
    41,42,43,44,0,0,
    29,30,31,32,46,47,
    37,38,39,40,0,0
};
__constant__ int c_psize[P_] = {5,6,4,6,4,5,6,4,6,4};

// Scratch (alloc-free rule: __device__ globals). Layout: [n][p][c]
__device__ float g_avg [N_ * P_ * C_];
__device__ float g_max [N_ * P_ * C_];
__device__ float g_gate[N_ * P_ * C_];

// ---------------------------------------------------------------------------
// Kernel 1: per-(n,c) sum+max over (t, v in part) for all 10 parts.
// One WARP per (n,c) slab; lanes 0..24 own a column-pair as float2.
// (Best measured variant: 36.0us, 74.9% DRAM.)
// ---------------------------------------------------------------------------
__global__ __launch_bounds__(256)
void reduce_kernel(const float2* __restrict__ x2)
{
    __shared__ float cs [8][V_ + 2];
    __shared__ float cmx[8][V_ + 2];

    const int warp = threadIdx.x >> 5;
    const int lane = threadIdx.x & 31;
    const int nc   = blockIdx.x * 8 + warp;          // n*C_ + c

    if (lane < 25) {
        const float2* p = x2 + (size_t)nc * (TV / 2) + lane;
        float sx = 0.f, sy = 0.f;
        float mx = -3.402823466e+38f, my = -3.402823466e+38f;
#pragma unroll 8
        for (int r = 0; r < T_; ++r) {
            float2 v = p[r * 25];
            sx += v.x;             sy += v.y;
            mx = fmaxf(mx, v.x);   my = fmaxf(my, v.y);
        }
        cs [warp][2 * lane]     = sx;
        cs [warp][2 * lane + 1] = sy;
        cmx[warp][2 * lane]     = mx;
        cmx[warp][2 * lane + 1] = my;
    }
    __syncwarp();

    if (lane < P_) {
        const int sz = c_psize[lane];
        float s3 = 0.f, m3 = -3.402823466e+38f;
        for (int j = 0; j < sz; ++j) {
            const int vv = c_pvs[lane * 6 + j];
            s3 += cs[warp][vv];
            m3 = fmaxf(m3, cmx[warp][vv]);
        }
        const int n = nc >> 8;      // C_ = 256
        const int c = nc & 255;
        const size_t o = ((size_t)n * P_ + lane) * C_ + c;
        g_avg[o] = s3 / (float)(T_ * sz);
        g_max[o] = m3;
    }
}

// ---------------------------------------------------------------------------
// Kernel 2: gate[n,p,c] = sigmoid( W2 @ (relu(W1@avg+b1)+relu(W1@mx+b1)) + 2*b2 )
// One block per (n,p), 256 threads.
// ---------------------------------------------------------------------------
__global__ __launch_bounds__(C_)
void gate_kernel(const float* __restrict__ W1, const float* __restrict__ b1,
                 const float* __restrict__ W2, const float* __restrict__ b2)
{
    const int np = blockIdx.x;
    const int n  = np / P_;
    const int p  = np % P_;
    const int tid = threadIdx.x;

    __shared__ float sa[C_];
    __shared__ float sx[C_];
    __shared__ float hs[H_];

    const size_t base = ((size_t)n * P_ + p) * C_;
    sa[tid] = g_avg[base + tid];
    sx[tid] = g_max[base + tid];
    __syncthreads();

    const int w = tid >> 5;     // warp 0..7
    const int l = tid & 31;

#pragma unroll
    for (int ii = 0; ii < 2; ++ii) {
        const int i = w + 8 * ii;
        const float* w1 = W1 + ((size_t)p * H_ + i) * C_;
        float da = 0.f, dm = 0.f;
#pragma unroll
        for (int k = 0; k < 8; ++k) {
            const int c = l + 32 * k;
            const float wv = w1[c];
            da += wv * sa[c];
            dm += wv * sx[c];
        }
#pragma unroll
        for (int off = 16; off > 0; off >>= 1) {
            da += __shfl_down_sync(0xffffffffu, da, off);
            dm += __shfl_down_sync(0xffffffffu, dm, off);
        }
        if (l == 0) {
            const float bb = b1[p * H_ + i];
            hs[i] = fmaxf(da + bb, 0.f) + fmaxf(dm + bb, 0.f);
        }
    }
    __syncthreads();

    const float* w2 = W2 + ((size_t)p * C_ + tid) * H_;
    float acc = 2.f * b2[p * C_ + tid];
#pragma unroll
    for (int k = 0; k < H_; ++k)
        acc += w2[k] * hs[k];

    g_gate[base + tid] = 1.f / (1.f + __expf(-acc));
}

// ---------------------------------------------------------------------------
// Kernel 3: out[n,c,t,j] = x[n,c,t,cmap[j]] * gate[n, pmap[j], c]
// smem-staged float4 reads, REVERSE block order (consume the x tail that
// reduce left in L2 first). Streaming stores.
// ---------------------------------------------------------------------------
__global__ __launch_bounds__(256)
void scale_kernel(const float4* __restrict__ x4, float* __restrict__ out)
{
    __shared__ float4 sh4[TV / 4];          // 12.8 KB
    __shared__ float2 tab[V_ + 2];          // {gate, int_as_float(cmap[j]-j)}
    float* sh = (float*)sh4;

    const int nc  = (N_ * C_ - 1) - blockIdx.x;      // REVERSE order
    const int tid = threadIdx.x;
    const int n = nc >> 8;
    const int c = nc & 255;

    const float4* xb = x4  + (size_t)nc * (TV / 4);
    float*        ob = out + (size_t)nc * TV;

    // Phase A: coalesced float4 loads into shared; threads <50 stage table
#pragma unroll
    for (int k = 0; k < 3; ++k)
        sh4[tid + 256 * k] = xb[tid + 256 * k];
    if (tid < 32)
        sh4[tid + 768] = xb[tid + 768];
    if (tid < V_) {
        const int j = tid;
        float2 t;
        t.x = g_gate[((size_t)n * P_ + c_pmap[j]) * C_ + c];
        t.y = __int_as_float(c_cmap[j] - j);
        tab[j] = t;
    }
    __syncthreads();

    // Phase B: lane-consecutive elements jj = tid + 256*m (3200 = 12*256+128)
    int col = tid % V_;                 // output column of element tid
#pragma unroll
    for (int m = 0; m < 13; ++m) {
        if (m < 12 || tid < 128) {
            const int jj = tid + 256 * m;
            const float2 t = tab[col];
            __stcs(&ob[jj], sh[jj + __float_as_int(t.y)] * t.x);
        }
        // advance column by 256 mod 50 = 6
        col += 6;
        if (col >= V_) col -= V_;
    }
}

// ---------------------------------------------------------------------------
extern "C" void kernel_launch(void* const* d_in, const int* in_sizes, int n_in,
                              void* d_out, int out_size)
{
    const float* x  = (const float*)d_in[0];
    const float* W1 = (const float*)d_in[1];
    const float* b1 = (const float*)d_in[2];
    const float* W2 = (const float*)d_in[3];
    const float* b2 = (const float*)d_in[4];

    reduce_kernel<<<(N_ * C_) / 8, 256>>>((const float2*)x);
    gate_kernel<<<N_ * P_, C_>>>(W1, b1, W2, b2);
    scale_kernel<<<N_ * C_, 256>>>((const float4*)x, (float*)d_out);
}